// round 13
// baseline (speedup 1.0000x reference)
#include <cuda_runtime.h>
#include <cuda_fp16.h>
#include <cstdint>
#include <math.h>

// ---------------- problem constants ----------------
#define TT   50
#define BB   2048
#define SST  256      // STATE
#define AAC  32       // ACTION
#define BEL  1024     // BELIEF
#define HID  1024     // HIDDEN
#define EMB  1024     // EMBED
#define KSA2 288      // STATE+ACTION (exact, 9 * 32)

// ================= scratch (device globals; no allocation allowed) =================
// fp16 hi/lo weights (hi+lo ~22-bit effective mantissa)
__device__ __align__(16) __half g_Wsa_h[1024 * KSA2], g_Wsa_l[1024 * KSA2];
__device__ __align__(16) __half g_Wih_h[3072 * 1024], g_Wih_l[3072 * 1024];
__device__ __align__(16) __half g_Whh_h[3072 * 1024], g_Whh_l[3072 * 1024];
__device__ __align__(16) __half g_Wpb_h[1024 * 1024], g_Wpb_l[1024 * 1024];
__device__ __align__(16) __half g_Wps_h[512 * 1024],  g_Wps_l[512 * 1024];
__device__ __align__(16) __half g_Wqb_h[1024 * 2048], g_Wqb_l[1024 * 2048];
__device__ __align__(16) __half g_Wqs_h[512 * 1024],  g_Wqs_l[512 * 1024];
// fp16 activations
__device__ __align__(16) __half g_act[TT * BB * AAC];
__device__ __align__(16) __half g_obs[TT * BB * EMB];
__device__ __align__(16) __half g_st[BB * SST];
__device__ __align__(16) __half g_rnn[BB * BEL];
__device__ __align__(16) __half g_bel[BB * BEL];
__device__ __align__(16) __half g_ph[BB * HID];
__device__ __align__(16) __half g_qh[BB * HID];
// fp32 scratch
__device__ __align__(16) float g_gi[BB * 3 * BEL];
__device__ __align__(16) float g_gh[BB * 3 * BEL];
__device__ __align__(16) float g_pout[BB * 2 * SST];
__device__ __align__(16) float g_qout[BB * 2 * SST];

// ================= low-level helpers (sm_80-baseline PTX only) =================
__device__ __forceinline__ uint32_t smem_u32(const void* p) {
    uint32_t a;
    asm("{ .reg .u64 t; cvta.to.shared.u64 t, %1; cvt.u32.u64 %0, t; }" : "=r"(a) : "l"(p));
    return a;
}
__device__ __forceinline__ void cp16(uint32_t dst, const void* src) {
    asm volatile("cp.async.cg.shared.global [%0], [%1], 16;" :: "r"(dst), "l"(src));
}
#define CP_COMMIT()  asm volatile("cp.async.commit_group;" ::: "memory")
#define CP_WAIT3()   asm volatile("cp.async.wait_group 3;" ::: "memory")

__device__ __forceinline__ void ldsm4(uint32_t* r, uint32_t addr) {
    asm volatile("ldmatrix.sync.aligned.m8n8.x4.shared.b16 {%0,%1,%2,%3}, [%4];"
                 : "=r"(r[0]), "=r"(r[1]), "=r"(r[2]), "=r"(r[3]) : "r"(addr));
}
__device__ __forceinline__ void mma16816(float* c, const uint32_t* a, uint32_t b0, uint32_t b1) {
    asm volatile(
        "mma.sync.aligned.m16n8k16.row.col.f32.f16.f16.f32 "
        "{%0,%1,%2,%3}, {%4,%5,%6,%7}, {%8,%9}, {%0,%1,%2,%3};"
        : "+f"(c[0]), "+f"(c[1]), "+f"(c[2]), "+f"(c[3])
        : "r"(a[0]), "r"(a[1]), "r"(a[2]), "r"(a[3]), "r"(b0), "r"(b1));
}

// ================= GEMM parameter block (per grid.z) =================
struct GArg {
    const __half *A0;                  // A source 0 (cols [0, K0))
    const __half *A1;                  // A source 1 (cols [K0, K)) or null
    int lda0, lda1, K0, K;
    const __half *Wh, *Wl;             // W [N, K] row-major, fp16 hi/lo
    int ldw;
    const float* bias;
    float* C;                          // fp32 out (if !HOUT)
    __half* Ch;                        // fp16 out (if HOUT)
    int N;
};

// ================= warp-MMA split-fp16 GEMM =================
// C[2048, N] = act( [A0|A1] @ (Wh+Wl)^T + bias ), 2-term: A*Wh + A*Wl, fp32 acc.
// CTA 128x128, 8 warps (4M x 2N), warp tile 32x64, BK=32, 5-stage cp.async, occ 1,
// single barrier per K-chunk (top-sync alone is sufficient; see R13 proof).
#define LDSW    40                       // smem row stride in fp16 (32 + 8 pad)
#define TSB     (128 * LDSW * 2)         // tile bytes (10240)
#define STAGE_B (3u * TSB)               // A, Wh, Wl (30720 B)
#define NSTAGE  5
#define SMEM_SZ (NSTAGE * STAGE_B)       // 153600 B -> 1 CTA/SM

__device__ __forceinline__ void load_stage(uint32_t sbase, const GArg& g,
                                           int row0, int col0, int kk, int tid)
{
    const __half *ap; int la, ko;
    if (kk < g.K0) { ap = g.A0; la = g.lda0; ko = kk; }
    else           { ap = g.A1; la = g.lda1; ko = kk - g.K0; }

    const int r  = tid >> 2;          // 0..63 (rows; x2 iters)
    const int c4 = tid & 3;           // 16B chunk within 32 cols
#pragma unroll
    for (int i = 0; i < 2; i++) {
        const int rr = i * 64 + r;
        const uint32_t so = (uint32_t)(rr * (LDSW * 2) + c4 * 16);
        cp16(sbase + so,            ap   + (size_t)(row0 + rr) * la    + ko + c4 * 8);
        cp16(sbase + TSB + so,      g.Wh + (size_t)(col0 + rr) * g.ldw + kk + c4 * 8);
        cp16(sbase + 2 * TSB + so,  g.Wl + (size_t)(col0 + rr) * g.ldw + kk + c4 * 8);
    }
}

template <bool RELU, bool HOUT>
__global__ __launch_bounds__(256, 1)
void mma_gemm2(GArg ga, GArg gb)
{
    const GArg g = (blockIdx.z == 0) ? ga : gb;

    extern __shared__ char smem_raw[];
    const uint32_t sb0 = smem_u32(smem_raw);

    const int tid = threadIdx.x;
    const int lane = tid & 31, wid = tid >> 5;
    const int wm = wid & 3, wn = wid >> 2;          // 4 x 2 warp grid
    const int row0 = blockIdx.y * 128, col0 = blockIdx.x * 128;

    float acc[2][8][4];
#pragma unroll
    for (int a = 0; a < 2; a++)
#pragma unroll
        for (int b = 0; b < 8; b++)
#pragma unroll
            for (int c = 0; c < 4; c++) acc[a][b][c] = 0.0f;

    const int NC = g.K / 32;   // min K = 288 -> NC = 9 >= NSTAGE - 1

    // prefetch stages 0..NSTAGE-2
#pragma unroll
    for (int s = 0; s < NSTAGE - 1; s++) {
        load_stage(sb0 + (uint32_t)s * STAGE_B, g, row0, col0, s * 32, tid);
        CP_COMMIT();
    }

    const int lrow = lane & 15;
    const int lcol = (lane >> 4) << 3;

    for (int c = 0; c < NC; c++) {
        CP_WAIT3();            // stage c complete for this thread
        __syncthreads();       // all threads' stage-c copies visible; iter c-1 compute done

        // prefetch stage c+4 (same buffer as c-1, safe after top sync)
        const int pf = c + NSTAGE - 1;
        if (pf < NC)
            load_stage(sb0 + (uint32_t)(pf % NSTAGE) * STAGE_B, g, row0, col0, pf * 32, tid);
        CP_COMMIT();

        const uint32_t st = sb0 + (uint32_t)(c % NSTAGE) * STAGE_B;
#pragma unroll
        for (int k16 = 0; k16 < 32; k16 += 16) {
            uint32_t av[2][4], wh[4][4], wl[4][4];
            // phase 1: A + Wh fragments, then all Wh MMAs (short ldsm->mma path)
#pragma unroll
            for (int mt = 0; mt < 2; mt++) {
                uint32_t ra = (uint32_t)((wm * 32 + mt * 16 + lrow) * LDSW + k16 + lcol) * 2;
                ldsm4(av[mt], st + ra);
            }
#pragma unroll
            for (int gg = 0; gg < 4; gg++) {
                uint32_t rb = (uint32_t)((wn * 64 + gg * 16 + lrow) * LDSW + k16 + lcol) * 2;
                ldsm4(wh[gg], st + TSB + rb);
            }
#pragma unroll
            for (int gg = 0; gg < 4; gg++) {
                uint32_t rb = (uint32_t)((wn * 64 + gg * 16 + lrow) * LDSW + k16 + lcol) * 2;
                ldsm4(wl[gg], st + 2 * TSB + rb);
            }
#pragma unroll
            for (int mt = 0; mt < 2; mt++)
#pragma unroll
                for (int gg = 0; gg < 4; gg++)
#pragma unroll
                    for (int h = 0; h < 2; h++)
                        mma16816(acc[mt][gg * 2 + h], av[mt], wh[gg][h], wh[gg][h + 2]);
            // phase 2: Wl MMAs (ldsm for wl overlapped with wh MMAs above)
#pragma unroll
            for (int mt = 0; mt < 2; mt++)
#pragma unroll
                for (int gg = 0; gg < 4; gg++)
#pragma unroll
                    for (int h = 0; h < 2; h++)
                        mma16816(acc[mt][gg * 2 + h], av[mt], wl[gg][h], wl[gg][h + 2]);
        }
        // no end-of-loop sync: next iteration's top sync provides the WAR barrier
    }

    // ---- epilogue (vectorized stores) ----
    const int gid = lane >> 2, tig = lane & 3;
#pragma unroll
    for (int mt = 0; mt < 2; mt++) {
        const int ra = row0 + wm * 32 + mt * 16 + gid;
#pragma unroll
        for (int nt = 0; nt < 8; nt++) {
            const int col = col0 + wn * 64 + nt * 8 + tig * 2;
            const float b0 = g.bias[col], b1 = g.bias[col + 1];
            const float* cc = acc[mt][nt];
#pragma unroll
            for (int half = 0; half < 2; half++) {
                const int r = ra + half * 8;
                float v0 = cc[half * 2 + 0] + b0;
                float v1 = cc[half * 2 + 1] + b1;
                if (RELU) { v0 = fmaxf(v0, 0.0f); v1 = fmaxf(v1, 0.0f); }
                const size_t o = (size_t)r * g.N + col;
                if (HOUT) {
                    *reinterpret_cast<__half2*>(g.Ch + o) = __floats2half2_rn(v0, v1);
                } else {
                    *reinterpret_cast<float2*>(g.C + o) = make_float2(v0, v1);
                }
            }
        }
    }
}

// ================= merged conversion kernels =================
struct WSeg { const float* src[7]; __half* hi[7]; __half* lo[7]; int blk0[8]; int size[7]; };
__global__ void conv_wsplit_all(WSeg a)
{
    int blk = blockIdx.x, s = 0;
#pragma unroll
    for (int i = 1; i < 7; i++) if (blk >= a.blk0[i]) s = i;
    int i = (blk - a.blk0[s]) * 256 + threadIdx.x;
    if (i < a.size[s]) {
        float x = a.src[s][i];
        __half h = __float2half_rn(x);
        a.hi[s][i] = h;
        a.lo[s][i] = __float2half_rn(x - __half2float(h));
    }
}

struct HSeg { const float* src[4]; __half* dst[4]; int blk0[5]; int size[4]; };
__global__ void conv_h_all(HSeg a)
{
    int blk = blockIdx.x, s = 0;
#pragma unroll
    for (int i = 1; i < 4; i++) if (blk >= a.blk0[i]) s = i;
    int i = (blk - a.blk0[s]) * 256 + threadIdx.x;
    if (i < a.size[s]) a.dst[s][i] = __float2half_rn(a.src[s][i]);
}

// ================= elementwise step kernels =================
__global__ void gru_combine(const float* __restrict__ gi, const float* __restrict__ gh,
                            const float* __restrict__ hprev, float* __restrict__ hout,
                            __half* __restrict__ bel_half)
{
    int i = blockIdx.x * blockDim.x + threadIdx.x;
    if (i >= BB * BEL) return;
    int b = i >> 10, c = i & 1023;
    const float* gib = gi + (size_t)b * 3 * BEL;
    const float* ghb = gh + (size_t)b * 3 * BEL;
    float ir = gib[c],           hr = ghb[c];
    float iz = gib[BEL + c],     hz = ghb[BEL + c];
    float in = gib[2 * BEL + c], hn = ghb[2 * BEL + c];
    float r = 1.0f / (1.0f + expf(-(ir + hr)));
    float z = 1.0f / (1.0f + expf(-(iz + hz)));
    float n = tanhf(in + r * hn);
    float h = (1.0f - z) * n + z * hprev[i];
    hout[i] = h;
    bel_half[i] = __float2half_rn(h);
}

__global__ void head_epi2(const float* __restrict__ pout, const float* __restrict__ qout,
                          const float* __restrict__ pn, const float* __restrict__ qn,
                          float* __restrict__ o_ps, float* __restrict__ o_pm, float* __restrict__ o_pstd,
                          float* __restrict__ o_qs, float* __restrict__ o_qm, float* __restrict__ o_qstd,
                          __half* __restrict__ st_half)
{
    int i = blockIdx.x * blockDim.x + threadIdx.x;
    if (i >= 2 * BB * SST) return;
    const bool isq = i >= BB * SST;
    const int j = isq ? i - BB * SST : i;
    const int b = j >> 8, c = j & 255;
    const float* src = isq ? qout : pout;
    float m  = src[(size_t)b * 2 * SST + c];
    float lg = src[(size_t)b * 2 * SST + SST + c];
    float y  = expf(lg);
    float sp = (y > 20.0f) ? y : log1pf(expf(y));
    float sd = sp + 0.1f;
    float ns = isq ? qn[j] : pn[j];
    float stv = m + sd * ns;
    if (isq) {
        o_qm[j] = m; o_qstd[j] = sd; o_qs[j] = stv;
        st_half[j] = __float2half_rn(stv);
    } else {
        o_pm[j] = m; o_pstd[j] = sd; o_ps[j] = stv;
    }
}

// ================= host dispatch =================
static inline GArg mk(const __half* A0, int lda0, int K0,
                      const __half* A1, int lda1, int K,
                      const __half* Wh, const __half* Wl, int ldw,
                      const float* bias, int N,
                      float* C, __half* Ch)
{
    GArg g;
    g.A0 = A0; g.A1 = A1;
    g.lda0 = lda0; g.lda1 = lda1; g.K0 = K0; g.K = K;
    g.Wh = Wh; g.Wl = Wl; g.ldw = ldw; g.bias = bias;
    g.C = C; g.Ch = Ch; g.N = N;
    return g;
}

extern "C" void kernel_launch(void* const* d_in, const int* in_sizes, int n_in,
                              void* d_out, int out_size)
{
    const float* prev_state   = (const float*)d_in[0];
    const float* actions      = (const float*)d_in[1];
    const float* prev_belief  = (const float*)d_in[2];
    const float* observations = (const float*)d_in[3];
    const float* prior_noise  = (const float*)d_in[4];
    const float* post_noise   = (const float*)d_in[5];
    const float* W_sa = (const float*)d_in[6];
    const float* b_sa = (const float*)d_in[7];
    const float* W_ih = (const float*)d_in[8];
    const float* W_hh = (const float*)d_in[9];
    const float* b_ih = (const float*)d_in[10];
    const float* b_hh = (const float*)d_in[11];
    const float* W_pb = (const float*)d_in[12];
    const float* b_pb = (const float*)d_in[13];
    const float* W_ps = (const float*)d_in[14];
    const float* b_ps = (const float*)d_in[15];
    const float* W_qb = (const float*)d_in[16];
    const float* b_qb = (const float*)d_in[17];
    const float* W_qs = (const float*)d_in[18];
    const float* b_qs = (const float*)d_in[19];

    float* out = (float*)d_out;
    float* out_bel  = out;
    float* out_ps   = out_bel  + (size_t)TT * BB * BEL;
    float* out_pm   = out_ps   + (size_t)TT * BB * SST;
    float* out_pstd = out_pm   + (size_t)TT * BB * SST;
    float* out_qs   = out_pstd + (size_t)TT * BB * SST;
    float* out_qm   = out_qs   + (size_t)TT * BB * SST;
    float* out_qstd = out_qm   + (size_t)TT * BB * SST;

    cudaFuncSetAttribute(mma_gemm2<true, true>,   cudaFuncAttributeMaxDynamicSharedMemorySize, SMEM_SZ);
    cudaFuncSetAttribute(mma_gemm2<false, false>, cudaFuncAttributeMaxDynamicSharedMemorySize, SMEM_SZ);

    __half *Wsa_h, *Wsa_l, *Wih_h, *Wih_l, *Whh_h, *Whh_l, *Wpb_h, *Wpb_l,
           *Wps_h, *Wps_l, *Wqb_h, *Wqb_l, *Wqs_h, *Wqs_l,
           *act, *obs, *st, *rnn, *bel, *ph, *qh;
    float *gi, *gh, *pout, *qout;
    cudaGetSymbolAddress((void**)&Wsa_h, g_Wsa_h); cudaGetSymbolAddress((void**)&Wsa_l, g_Wsa_l);
    cudaGetSymbolAddress((void**)&Wih_h, g_Wih_h); cudaGetSymbolAddress((void**)&Wih_l, g_Wih_l);
    cudaGetSymbolAddress((void**)&Whh_h, g_Whh_h); cudaGetSymbolAddress((void**)&Whh_l, g_Whh_l);
    cudaGetSymbolAddress((void**)&Wpb_h, g_Wpb_h); cudaGetSymbolAddress((void**)&Wpb_l, g_Wpb_l);
    cudaGetSymbolAddress((void**)&Wps_h, g_Wps_h); cudaGetSymbolAddress((void**)&Wps_l, g_Wps_l);
    cudaGetSymbolAddress((void**)&Wqb_h, g_Wqb_h); cudaGetSymbolAddress((void**)&Wqb_l, g_Wqb_l);
    cudaGetSymbolAddress((void**)&Wqs_h, g_Wqs_h); cudaGetSymbolAddress((void**)&Wqs_l, g_Wqs_l);
    cudaGetSymbolAddress((void**)&act, g_act); cudaGetSymbolAddress((void**)&obs, g_obs);
    cudaGetSymbolAddress((void**)&st,  g_st);  cudaGetSymbolAddress((void**)&rnn, g_rnn);
    cudaGetSymbolAddress((void**)&bel, g_bel); cudaGetSymbolAddress((void**)&ph,  g_ph);
    cudaGetSymbolAddress((void**)&qh,  g_qh);
    cudaGetSymbolAddress((void**)&gi,   g_gi);   cudaGetSymbolAddress((void**)&gh,   g_gh);
    cudaGetSymbolAddress((void**)&pout, g_pout); cudaGetSymbolAddress((void**)&qout, g_qout);

    // ---- merged one-time conversions (2 launches) ----
    {
        WSeg w;
        const float* srcs[7] = {W_sa, W_ih, W_hh, W_pb, W_ps, W_qb, W_qs};
        __half* his[7] = {Wsa_h, Wih_h, Whh_h, Wpb_h, Wps_h, Wqb_h, Wqs_h};
        __half* los[7] = {Wsa_l, Wih_l, Whh_l, Wpb_l, Wps_l, Wqb_l, Wqs_l};
        int sizes[7] = {1024 * KSA2, 3072 * 1024, 3072 * 1024, 1024 * 1024,
                        512 * 1024, 1024 * 2048, 512 * 1024};
        int cum = 0;
        for (int i = 0; i < 7; i++) {
            w.src[i] = srcs[i]; w.hi[i] = his[i]; w.lo[i] = los[i]; w.size[i] = sizes[i];
            w.blk0[i] = cum; cum += (sizes[i] + 255) / 256;
        }
        w.blk0[7] = cum;
        conv_wsplit_all<<<cum, 256>>>(w);
    }
    {
        HSeg h;
        const float* srcs[4] = {actions, observations, prev_state, prev_belief};
        __half* dsts[4] = {act, obs, st, bel};
        int sizes[4] = {TT * BB * AAC, TT * BB * EMB, BB * SST, BB * BEL};
        int cum = 0;
        for (int i = 0; i < 4; i++) {
            h.src[i] = srcs[i]; h.dst[i] = dsts[i]; h.size[i] = sizes[i];
            h.blk0[i] = cum; cum += (sizes[i] + 255) / 256;
        }
        h.blk0[4] = cum;
        conv_h_all<<<cum, 256>>>(h);
    }

    const dim3 g_sa(8, 16, 1), g_gate(24, 16, 2), g_pq(8, 16, 2), g_ss(4, 16, 2);
    const int nb_bel = (BB * BEL) / 256, nb_head2 = (2 * BB * SST) / 256;

    for (int t = 0; t < TT; t++) {
        const __half* a_t = act + (size_t)t * BB * AAC;
        const __half* o_t = obs + (size_t)t * BB * EMB;
        const float* pn_t = prior_noise + (size_t)t * BB * SST;
        const float* qn_t = post_noise  + (size_t)t * BB * SST;
        const float* bel_prev_f32 = (t == 0) ? prev_belief
                                             : out_bel + (size_t)(t - 1) * BB * BEL;
        float* bel_t = out_bel + (size_t)t * BB * BEL;

        // 1. rnn_in = relu([state | action] @ W_sa^T + b_sa) -> fp16
        {
            GArg a = mk(st, SST, SST, a_t, AAC, KSA2,
                        Wsa_h, Wsa_l, KSA2, b_sa, BEL, nullptr, rnn);
            mma_gemm2<true, true><<<g_sa, 256, SMEM_SZ>>>(a, a);
        }
        // 2. GRU gates, batched: z0 gi = rnn@W_ih^T, z1 gh = bel@W_hh^T
        {
            GArg a = mk(rnn, BEL, BEL, nullptr, 0, BEL,
                        Wih_h, Wih_l, BEL, b_ih, 3 * BEL, gi, nullptr);
            GArg b = mk(bel, BEL, BEL, nullptr, 0, BEL,
                        Whh_h, Whh_l, BEL, b_hh, 3 * BEL, gh, nullptr);
            mma_gemm2<false, false><<<g_gate, 256, SMEM_SZ>>>(a, b);
        }
        gru_combine<<<nb_bel, 256>>>(gi, gh, bel_prev_f32, bel_t, bel);

        // 3. hidden heads, batched: z0 ph = relu(bel@W_pb^T), z1 qh = relu([bel|obs]@W_qb^T)
        {
            GArg a = mk(bel, BEL, BEL, nullptr, 0, BEL,
                        Wpb_h, Wpb_l, BEL, b_pb, HID, nullptr, ph);
            GArg b = mk(bel, BEL, BEL, o_t, EMB, BEL + EMB,
                        Wqb_h, Wqb_l, BEL + EMB, b_qb, HID, nullptr, qh);
            mma_gemm2<true, true><<<g_pq, 256, SMEM_SZ>>>(a, b);
        }
        // 4. stat heads, batched: z0 pout = ph@W_ps^T, z1 qout = qh@W_qs^T
        {
            GArg a = mk(ph, HID, HID, nullptr, 0, HID,
                        Wps_h, Wps_l, HID, b_ps, 2 * SST, pout, nullptr);
            GArg b = mk(qh, HID, HID, nullptr, 0, HID,
                        Wqs_h, Wqs_l, HID, b_qs, 2 * SST, qout, nullptr);
            mma_gemm2<false, false><<<g_ss, 256, SMEM_SZ>>>(a, b);
        }
        // 5. both head epilogues + next-step state
        head_epi2<<<nb_head2, 256>>>(pout, qout, pn_t, qn_t,
                                     out_ps   + (size_t)t * BB * SST,
                                     out_pm   + (size_t)t * BB * SST,
                                     out_pstd + (size_t)t * BB * SST,
                                     out_qs   + (size_t)t * BB * SST,
                                     out_qm   + (size_t)t * BB * SST,
                                     out_qstd + (size_t)t * BB * SST,
                                     st);
    }
}

// round 16
// speedup vs baseline: 1.0644x; 1.0644x over previous
#include <cuda_runtime.h>
#include <cuda_fp16.h>
#include <cstdint>
#include <math.h>

// ---------------- problem constants ----------------
#define TT   50
#define BB   2048
#define SST  256      // STATE
#define AAC  32       // ACTION
#define BEL  1024     // BELIEF
#define HID  1024     // HIDDEN
#define EMB  1024     // EMBED
#define KSA2 288      // STATE+ACTION (exact, 9 * 32)

// ================= scratch (device globals; no allocation allowed) =================
// fp16 hi/lo weights (hi+lo ~22-bit effective mantissa)
__device__ __align__(16) __half g_Wsa_h[1024 * KSA2], g_Wsa_l[1024 * KSA2];
__device__ __align__(16) __half g_Wih_h[3072 * 1024], g_Wih_l[3072 * 1024];
__device__ __align__(16) __half g_Whh_h[3072 * 1024], g_Whh_l[3072 * 1024];
__device__ __align__(16) __half g_Wpb_h[1024 * 1024], g_Wpb_l[1024 * 1024];
__device__ __align__(16) __half g_Wps_h[512 * 1024],  g_Wps_l[512 * 1024];
__device__ __align__(16) __half g_Wqb_h[1024 * 2048], g_Wqb_l[1024 * 2048];
__device__ __align__(16) __half g_Wqs_h[512 * 1024],  g_Wqs_l[512 * 1024];
// fp16 activations
__device__ __align__(16) __half g_act[TT * BB * AAC];
__device__ __align__(16) __half g_obs[TT * BB * EMB];
__device__ __align__(16) __half g_st[BB * SST];
__device__ __align__(16) __half g_rnn[BB * BEL];
__device__ __align__(16) __half g_bel[BB * BEL];
__device__ __align__(16) __half g_ph[BB * HID];
__device__ __align__(16) __half g_qh[BB * HID];
// fp32 scratch
__device__ __align__(16) float g_gi[BB * 3 * BEL];
__device__ __align__(16) float g_gh[BB * 3 * BEL];
__device__ __align__(16) float g_pout[BB * 2 * SST];
__device__ __align__(16) float g_qout[BB * 2 * SST];

// ================= low-level helpers (sm_80-baseline PTX only) =================
__device__ __forceinline__ uint32_t smem_u32(const void* p) {
    uint32_t a;
    asm("{ .reg .u64 t; cvta.to.shared.u64 t, %1; cvt.u32.u64 %0, t; }" : "=r"(a) : "l"(p));
    return a;
}
__device__ __forceinline__ void cp16(uint32_t dst, const void* src) {
    asm volatile("cp.async.cg.shared.global [%0], [%1], 16;" :: "r"(dst), "l"(src));
}
#define CP_COMMIT()  asm volatile("cp.async.commit_group;" ::: "memory")
#define CP_WAIT3()   asm volatile("cp.async.wait_group 3;" ::: "memory")

__device__ __forceinline__ void ldsm4(uint32_t* r, uint32_t addr) {
    asm volatile("ldmatrix.sync.aligned.m8n8.x4.shared.b16 {%0,%1,%2,%3}, [%4];"
                 : "=r"(r[0]), "=r"(r[1]), "=r"(r[2]), "=r"(r[3]) : "r"(addr));
}
__device__ __forceinline__ void mma16816(float* c, const uint32_t* a, uint32_t b0, uint32_t b1) {
    asm volatile(
        "mma.sync.aligned.m16n8k16.row.col.f32.f16.f16.f32 "
        "{%0,%1,%2,%3}, {%4,%5,%6,%7}, {%8,%9}, {%0,%1,%2,%3};"
        : "+f"(c[0]), "+f"(c[1]), "+f"(c[2]), "+f"(c[3])
        : "r"(a[0]), "r"(a[1]), "r"(a[2]), "r"(a[3]), "r"(b0), "r"(b1));
}

// ================= GEMM parameter block (per grid.z) =================
struct GArg {
    const __half *A0;                  // A source 0 (cols [0, K0))
    const __half *A1;                  // A source 1 (cols [K0, K)) or null
    int lda0, lda1, K0, K;
    const __half *Wh, *Wl;             // W [N, K] row-major, fp16 hi/lo
    int ldw;
    const float* bias;
    float* C;                          // fp32 out (if !HOUT)
    __half* Ch;                        // fp16 out (if HOUT)
    int N;
};

// ================= warp-MMA split-fp16 GEMM =================
// C[2048, N] = act( [A0|A1] @ (Wh+Wl)^T + bias ), 2-term: A*Wh + A*Wl, fp32 acc.
// CTA tile 128x64 (M x N), 8 warps in 4M x 2N grid of 32x32 warp tiles, BK=32,
// 5-stage cp.async, 2 CTAs/SM (~95 regs, under the 128-reg occ-2 cap).
// Loader: each BK=32 fp16 row = 64 B = FOUR 16B chunks (c4 in 0..3).
#define LDSW    40                       // smem row stride in fp16 (32 + 8 pad)
#define TSA     (128 * LDSW * 2)         // A tile bytes (10240)
#define TSW     (64 * LDSW * 2)          // W tile bytes (5120)
#define STAGE_B (TSA + 2u * TSW)         // A, Wh, Wl (20480 B)
#define NSTAGE  5
#define SMEM_SZ (NSTAGE * STAGE_B)       // 102400 B -> 2 CTAs/SM

__device__ __forceinline__ void load_stage(uint32_t sbase, const GArg& g,
                                           int row0, int col0, int kk, int tid)
{
    const __half *ap; int la, ko;
    if (kk < g.K0) { ap = g.A0; la = g.lda0; ko = kk; }
    else           { ap = g.A1; la = g.lda1; ko = kk - g.K0; }

    // A: 128 rows x 4 16B-chunks = 512 cp16 (2 per thread)
#pragma unroll
    for (int i = 0; i < 2; i++) {
        const int idx = i * 256 + tid;
        const int r = idx >> 2, c4 = idx & 3;
        cp16(sbase + (uint32_t)(r * (LDSW * 2) + c4 * 16),
             ap + (size_t)(row0 + r) * la + ko + c4 * 8);
    }
    // Wh/Wl: 64 rows x 4 chunks each = 256 + 256 cp16 (1+1 per thread)
    {
        const int r = tid >> 2, c4 = tid & 3;
        const uint32_t so = (uint32_t)(r * (LDSW * 2) + c4 * 16);
        cp16(sbase + TSA + so,       g.Wh + (size_t)(col0 + r) * g.ldw + kk + c4 * 8);
        cp16(sbase + TSA + TSW + so, g.Wl + (size_t)(col0 + r) * g.ldw + kk + c4 * 8);
    }
}

template <bool RELU, bool HOUT>
__global__ __launch_bounds__(256, 2)
void mma_gemm2(GArg ga, GArg gb)
{
    const GArg g = (blockIdx.z == 0) ? ga : gb;

    extern __shared__ char smem_raw[];
    const uint32_t sb0 = smem_u32(smem_raw);

    const int tid = threadIdx.x;
    const int lane = tid & 31, wid = tid >> 5;
    const int wm = wid & 3, wn = wid >> 2;          // 4M x 2N warp grid, 32x32 tiles
    const int row0 = blockIdx.y * 128, col0 = blockIdx.x * 64;

    float acc[2][4][4];
#pragma unroll
    for (int a = 0; a < 2; a++)
#pragma unroll
        for (int b = 0; b < 4; b++)
#pragma unroll
            for (int c = 0; c < 4; c++) acc[a][b][c] = 0.0f;

    const int NC = g.K / 32;   // min K = 288 -> NC = 9 >= NSTAGE - 1

    // prefetch stages 0..NSTAGE-2
#pragma unroll
    for (int s = 0; s < NSTAGE - 1; s++) {
        load_stage(sb0 + (uint32_t)s * STAGE_B, g, row0, col0, s * 32, tid);
        CP_COMMIT();
    }

    const int lrow = lane & 15;
    const int lcol = (lane >> 4) << 3;

    for (int c = 0; c < NC; c++) {
        CP_WAIT3();            // stage c complete for this thread
        __syncthreads();       // stage-c visible to all; iter c-1 compute done

        // prefetch stage c+4 (same buffer as c-1; safe after top sync)
        const int pf = c + NSTAGE - 1;
        if (pf < NC)
            load_stage(sb0 + (uint32_t)(pf % NSTAGE) * STAGE_B, g, row0, col0, pf * 32, tid);
        CP_COMMIT();

        const uint32_t st = sb0 + (uint32_t)(c % NSTAGE) * STAGE_B;
#pragma unroll
        for (int k16 = 0; k16 < 32; k16 += 16) {
            uint32_t av[2][4], wh[2][4], wl[2][4];
#pragma unroll
            for (int mt = 0; mt < 2; mt++) {
                uint32_t ra = (uint32_t)((wm * 32 + mt * 16 + lrow) * LDSW + k16 + lcol) * 2;
                ldsm4(av[mt], st + ra);
            }
#pragma unroll
            for (int gg = 0; gg < 2; gg++) {
                uint32_t rb = (uint32_t)((wn * 32 + gg * 16 + lrow) * LDSW + k16 + lcol) * 2;
                ldsm4(wh[gg], st + TSA + rb);
                ldsm4(wl[gg], st + TSA + TSW + rb);
            }
#pragma unroll
            for (int mt = 0; mt < 2; mt++)
#pragma unroll
                for (int gg = 0; gg < 2; gg++)
#pragma unroll
                    for (int h = 0; h < 2; h++)
                        mma16816(acc[mt][gg * 2 + h], av[mt], wh[gg][h], wh[gg][h + 2]);
#pragma unroll
            for (int mt = 0; mt < 2; mt++)
#pragma unroll
                for (int gg = 0; gg < 2; gg++)
#pragma unroll
                    for (int h = 0; h < 2; h++)
                        mma16816(acc[mt][gg * 2 + h], av[mt], wl[gg][h], wl[gg][h + 2]);
        }
        // no end-of-loop sync: next iteration's top sync provides the WAR barrier
    }

    // ---- epilogue (vectorized stores) ----
    const int gid = lane >> 2, tig = lane & 3;
#pragma unroll
    for (int mt = 0; mt < 2; mt++) {
        const int ra = row0 + wm * 32 + mt * 16 + gid;
#pragma unroll
        for (int nt = 0; nt < 4; nt++) {
            const int col = col0 + wn * 32 + nt * 8 + tig * 2;
            const float b0 = g.bias[col], b1 = g.bias[col + 1];
            const float* cc = acc[mt][nt];
#pragma unroll
            for (int half = 0; half < 2; half++) {
                const int r = ra + half * 8;
                float v0 = cc[half * 2 + 0] + b0;
                float v1 = cc[half * 2 + 1] + b1;
                if (RELU) { v0 = fmaxf(v0, 0.0f); v1 = fmaxf(v1, 0.0f); }
                const size_t o = (size_t)r * g.N + col;
                if (HOUT) {
                    *reinterpret_cast<__half2*>(g.Ch + o) = __floats2half2_rn(v0, v1);
                } else {
                    *reinterpret_cast<float2*>(g.C + o) = make_float2(v0, v1);
                }
            }
        }
    }
}

// ================= merged conversion kernels =================
struct WSeg { const float* src[7]; __half* hi[7]; __half* lo[7]; int blk0[8]; int size[7]; };
__global__ void conv_wsplit_all(WSeg a)
{
    int blk = blockIdx.x, s = 0;
#pragma unroll
    for (int i = 1; i < 7; i++) if (blk >= a.blk0[i]) s = i;
    int i = (blk - a.blk0[s]) * 256 + threadIdx.x;
    if (i < a.size[s]) {
        float x = a.src[s][i];
        __half h = __float2half_rn(x);
        a.hi[s][i] = h;
        a.lo[s][i] = __float2half_rn(x - __half2float(h));
    }
}

struct HSeg { const float* src[4]; __half* dst[4]; int blk0[5]; int size[4]; };
__global__ void conv_h_all(HSeg a)
{
    int blk = blockIdx.x, s = 0;
#pragma unroll
    for (int i = 1; i < 4; i++) if (blk >= a.blk0[i]) s = i;
    int i = (blk - a.blk0[s]) * 256 + threadIdx.x;
    if (i < a.size[s]) a.dst[s][i] = __float2half_rn(a.src[s][i]);
}

// ================= elementwise step kernels =================
__global__ void gru_combine(const float* __restrict__ gi, const float* __restrict__ gh,
                            const float* __restrict__ hprev, float* __restrict__ hout,
                            __half* __restrict__ bel_half)
{
    int i = blockIdx.x * blockDim.x + threadIdx.x;
    if (i >= BB * BEL) return;
    int b = i >> 10, c = i & 1023;
    const float* gib = gi + (size_t)b * 3 * BEL;
    const float* ghb = gh + (size_t)b * 3 * BEL;
    float ir = gib[c],           hr = ghb[c];
    float iz = gib[BEL + c],     hz = ghb[BEL + c];
    float in = gib[2 * BEL + c], hn = ghb[2 * BEL + c];
    float r = 1.0f / (1.0f + expf(-(ir + hr)));
    float z = 1.0f / (1.0f + expf(-(iz + hz)));
    float n = tanhf(in + r * hn);
    float h = (1.0f - z) * n + z * hprev[i];
    hout[i] = h;
    bel_half[i] = __float2half_rn(h);
}

__global__ void head_epi2(const float* __restrict__ pout, const float* __restrict__ qout,
                          const float* __restrict__ pn, const float* __restrict__ qn,
                          float* __restrict__ o_ps, float* __restrict__ o_pm, float* __restrict__ o_pstd,
                          float* __restrict__ o_qs, float* __restrict__ o_qm, float* __restrict__ o_qstd,
                          __half* __restrict__ st_half)
{
    int i = blockIdx.x * blockDim.x + threadIdx.x;
    if (i >= 2 * BB * SST) return;
    const bool isq = i >= BB * SST;
    const int j = isq ? i - BB * SST : i;
    const int b = j >> 8, c = j & 255;
    const float* src = isq ? qout : pout;
    float m  = src[(size_t)b * 2 * SST + c];
    float lg = src[(size_t)b * 2 * SST + SST + c];
    float y  = expf(lg);
    float sp = (y > 20.0f) ? y : log1pf(expf(y));
    float sd = sp + 0.1f;
    float ns = isq ? qn[j] : pn[j];
    float stv = m + sd * ns;
    if (isq) {
        o_qm[j] = m; o_qstd[j] = sd; o_qs[j] = stv;
        st_half[j] = __float2half_rn(stv);
    } else {
        o_pm[j] = m; o_pstd[j] = sd; o_ps[j] = stv;
    }
}

// ================= host dispatch =================
static inline GArg mk(const __half* A0, int lda0, int K0,
                      const __half* A1, int lda1, int K,
                      const __half* Wh, const __half* Wl, int ldw,
                      const float* bias, int N,
                      float* C, __half* Ch)
{
    GArg g;
    g.A0 = A0; g.A1 = A1;
    g.lda0 = lda0; g.lda1 = lda1; g.K0 = K0; g.K = K;
    g.Wh = Wh; g.Wl = Wl; g.ldw = ldw; g.bias = bias;
    g.C = C; g.Ch = Ch; g.N = N;
    return g;
}

extern "C" void kernel_launch(void* const* d_in, const int* in_sizes, int n_in,
                              void* d_out, int out_size)
{
    const float* prev_state   = (const float*)d_in[0];
    const float* actions      = (const float*)d_in[1];
    const float* prev_belief  = (const float*)d_in[2];
    const float* observations = (const float*)d_in[3];
    const float* prior_noise  = (const float*)d_in[4];
    const float* post_noise   = (const float*)d_in[5];
    const float* W_sa = (const float*)d_in[6];
    const float* b_sa = (const float*)d_in[7];
    const float* W_ih = (const float*)d_in[8];
    const float* W_hh = (const float*)d_in[9];
    const float* b_ih = (const float*)d_in[10];
    const float* b_hh = (const float*)d_in[11];
    const float* W_pb = (const float*)d_in[12];
    const float* b_pb = (const float*)d_in[13];
    const float* W_ps = (const float*)d_in[14];
    const float* b_ps = (const float*)d_in[15];
    const float* W_qb = (const float*)d_in[16];
    const float* b_qb = (const float*)d_in[17];
    const float* W_qs = (const float*)d_in[18];
    const float* b_qs = (const float*)d_in[19];

    float* out = (float*)d_out;
    float* out_bel  = out;
    float* out_ps   = out_bel  + (size_t)TT * BB * BEL;
    float* out_pm   = out_ps   + (size_t)TT * BB * SST;
    float* out_pstd = out_pm   + (size_t)TT * BB * SST;
    float* out_qs   = out_pstd + (size_t)TT * BB * SST;
    float* out_qm   = out_qs   + (size_t)TT * BB * SST;
    float* out_qstd = out_qm   + (size_t)TT * BB * SST;

    cudaFuncSetAttribute(mma_gemm2<true, true>,   cudaFuncAttributeMaxDynamicSharedMemorySize, SMEM_SZ);
    cudaFuncSetAttribute(mma_gemm2<false, false>, cudaFuncAttributeMaxDynamicSharedMemorySize, SMEM_SZ);

    __half *Wsa_h, *Wsa_l, *Wih_h, *Wih_l, *Whh_h, *Whh_l, *Wpb_h, *Wpb_l,
           *Wps_h, *Wps_l, *Wqb_h, *Wqb_l, *Wqs_h, *Wqs_l,
           *act, *obs, *st, *rnn, *bel, *ph, *qh;
    float *gi, *gh, *pout, *qout;
    cudaGetSymbolAddress((void**)&Wsa_h, g_Wsa_h); cudaGetSymbolAddress((void**)&Wsa_l, g_Wsa_l);
    cudaGetSymbolAddress((void**)&Wih_h, g_Wih_h); cudaGetSymbolAddress((void**)&Wih_l, g_Wih_l);
    cudaGetSymbolAddress((void**)&Whh_h, g_Whh_h); cudaGetSymbolAddress((void**)&Whh_l, g_Whh_l);
    cudaGetSymbolAddress((void**)&Wpb_h, g_Wpb_h); cudaGetSymbolAddress((void**)&Wpb_l, g_Wpb_l);
    cudaGetSymbolAddress((void**)&Wps_h, g_Wps_h); cudaGetSymbolAddress((void**)&Wps_l, g_Wps_l);
    cudaGetSymbolAddress((void**)&Wqb_h, g_Wqb_h); cudaGetSymbolAddress((void**)&Wqb_l, g_Wqb_l);
    cudaGetSymbolAddress((void**)&Wqs_h, g_Wqs_h); cudaGetSymbolAddress((void**)&Wqs_l, g_Wqs_l);
    cudaGetSymbolAddress((void**)&act, g_act); cudaGetSymbolAddress((void**)&obs, g_obs);
    cudaGetSymbolAddress((void**)&st,  g_st);  cudaGetSymbolAddress((void**)&rnn, g_rnn);
    cudaGetSymbolAddress((void**)&bel, g_bel); cudaGetSymbolAddress((void**)&ph,  g_ph);
    cudaGetSymbolAddress((void**)&qh,  g_qh);
    cudaGetSymbolAddress((void**)&gi,   g_gi);   cudaGetSymbolAddress((void**)&gh,   g_gh);
    cudaGetSymbolAddress((void**)&pout, g_pout); cudaGetSymbolAddress((void**)&qout, g_qout);

    // ---- merged one-time conversions (2 launches) ----
    {
        WSeg w;
        const float* srcs[7] = {W_sa, W_ih, W_hh, W_pb, W_ps, W_qb, W_qs};
        __half* his[7] = {Wsa_h, Wih_h, Whh_h, Wpb_h, Wps_h, Wqb_h, Wqs_h};
        __half* los[7] = {Wsa_l, Wih_l, Whh_l, Wpb_l, Wps_l, Wqb_l, Wqs_l};
        int sizes[7] = {1024 * KSA2, 3072 * 1024, 3072 * 1024, 1024 * 1024,
                        512 * 1024, 1024 * 2048, 512 * 1024};
        int cum = 0;
        for (int i = 0; i < 7; i++) {
            w.src[i] = srcs[i]; w.hi[i] = his[i]; w.lo[i] = los[i]; w.size[i] = sizes[i];
            w.blk0[i] = cum; cum += (sizes[i] + 255) / 256;
        }
        w.blk0[7] = cum;
        conv_wsplit_all<<<cum, 256>>>(w);
    }
    {
        HSeg h;
        const float* srcs[4] = {actions, observations, prev_state, prev_belief};
        __half* dsts[4] = {act, obs, st, bel};
        int sizes[4] = {TT * BB * AAC, TT * BB * EMB, BB * SST, BB * BEL};
        int cum = 0;
        for (int i = 0; i < 4; i++) {
            h.src[i] = srcs[i]; h.dst[i] = dsts[i]; h.size[i] = sizes[i];
            h.blk0[i] = cum; cum += (sizes[i] + 255) / 256;
        }
        h.blk0[4] = cum;
        conv_h_all<<<cum, 256>>>(h);
    }

    // grids: x = N/64, y = M/128, z = batched pair
    const dim3 g_sa(16, 16, 1), g_gate(48, 16, 2), g_pq(16, 16, 2), g_ss(8, 16, 2);
    const int nb_bel = (BB * BEL) / 256, nb_head2 = (2 * BB * SST) / 256;

    for (int t = 0; t < TT; t++) {
        const __half* a_t = act + (size_t)t * BB * AAC;
        const __half* o_t = obs + (size_t)t * BB * EMB;
        const float* pn_t = prior_noise + (size_t)t * BB * SST;
        const float* qn_t = post_noise  + (size_t)t * BB * SST;
        const float* bel_prev_f32 = (t == 0) ? prev_belief
                                             : out_bel + (size_t)(t - 1) * BB * BEL;
        float* bel_t = out_bel + (size_t)t * BB * BEL;

        // 1. rnn_in = relu([state | action] @ W_sa^T + b_sa) -> fp16
        {
            GArg a = mk(st, SST, SST, a_t, AAC, KSA2,
                        Wsa_h, Wsa_l, KSA2, b_sa, BEL, nullptr, rnn);
            mma_gemm2<true, true><<<g_sa, 256, SMEM_SZ>>>(a, a);
        }
        // 2. GRU gates, batched: z0 gi = rnn@W_ih^T, z1 gh = bel@W_hh^T
        {
            GArg a = mk(rnn, BEL, BEL, nullptr, 0, BEL,
                        Wih_h, Wih_l, BEL, b_ih, 3 * BEL, gi, nullptr);
            GArg b = mk(bel, BEL, BEL, nullptr, 0, BEL,
                        Whh_h, Whh_l, BEL, b_hh, 3 * BEL, gh, nullptr);
            mma_gemm2<false, false><<<g_gate, 256, SMEM_SZ>>>(a, b);
        }
        gru_combine<<<nb_bel, 256>>>(gi, gh, bel_prev_f32, bel_t, bel);

        // 3. hidden heads, batched: z0 ph = relu(bel@W_pb^T), z1 qh = relu([bel|obs]@W_qb^T)
        {
            GArg a = mk(bel, BEL, BEL, nullptr, 0, BEL,
                        Wpb_h, Wpb_l, BEL, b_pb, HID, nullptr, ph);
            GArg b = mk(bel, BEL, BEL, o_t, EMB, BEL + EMB,
                        Wqb_h, Wqb_l, BEL + EMB, b_qb, HID, nullptr, qh);
            mma_gemm2<true, true><<<g_pq, 256, SMEM_SZ>>>(a, b);
        }
        // 4. stat heads, batched: z0 pout = ph@W_ps^T, z1 qout = qh@W_qs^T
        {
            GArg a = mk(ph, HID, HID, nullptr, 0, HID,
                        Wps_h, Wps_l, HID, b_ps, 2 * SST, pout, nullptr);
            GArg b = mk(qh, HID, HID, nullptr, 0, HID,
                        Wqs_h, Wqs_l, HID, b_qs, 2 * SST, qout, nullptr);
            mma_gemm2<false, false><<<g_ss, 256, SMEM_SZ>>>(a, b);
        }
        // 5. both head epilogues + next-step state
        head_epi2<<<nb_head2, 256>>>(pout, qout, pn_t, qn_t,
                                     out_ps   + (size_t)t * BB * SST,
                                     out_pm   + (size_t)t * BB * SST,
                                     out_pstd + (size_t)t * BB * SST,
                                     out_qs   + (size_t)t * BB * SST,
                                     out_qm   + (size_t)t * BB * SST,
                                     out_qstd + (size_t)t * BB * SST,
                                     st);
    }
}

// round 17
// speedup vs baseline: 1.1384x; 1.0696x over previous
#include <cuda_runtime.h>
#include <cuda_fp16.h>
#include <cstdint>
#include <math.h>

// ---------------- problem constants ----------------
#define TT   50
#define BB   2048
#define SST  256      // STATE
#define AAC  32       // ACTION
#define BEL  1024     // BELIEF
#define HID  1024     // HIDDEN
#define EMB  1024     // EMBED
#define KSA2 288      // STATE+ACTION (exact, 9 * 32)

// ================= scratch (device globals; no allocation allowed) =================
// fp16 hi/lo weights (hi+lo ~22-bit effective mantissa)
__device__ __align__(16) __half g_Wsa_h[1024 * KSA2], g_Wsa_l[1024 * KSA2];
__device__ __align__(16) __half g_Wih_h[3072 * 1024], g_Wih_l[3072 * 1024];
__device__ __align__(16) __half g_Whh_h[3072 * 1024], g_Whh_l[3072 * 1024];
__device__ __align__(16) __half g_Wpb_h[1024 * 1024], g_Wpb_l[1024 * 1024];
__device__ __align__(16) __half g_Wps_h[512 * 1024],  g_Wps_l[512 * 1024];
__device__ __align__(16) __half g_Wqb_h[1024 * 2048], g_Wqb_l[1024 * 2048];
__device__ __align__(16) __half g_Wqs_h[512 * 1024],  g_Wqs_l[512 * 1024];
// fp16 activations
__device__ __align__(16) __half g_act[TT * BB * AAC];
__device__ __align__(16) __half g_obs[TT * BB * EMB];
__device__ __align__(16) __half g_st[BB * SST];
__device__ __align__(16) __half g_rnn[BB * BEL];
__device__ __align__(16) __half g_bel[BB * BEL];
__device__ __align__(16) __half g_ph[BB * HID];
__device__ __align__(16) __half g_qh[BB * HID];
// fp32 scratch
__device__ __align__(16) float g_gi[BB * 3 * BEL];
__device__ __align__(16) float g_gh[BB * 3 * BEL];
__device__ __align__(16) float g_pout[BB * 2 * SST];
__device__ __align__(16) float g_qout[BB * 2 * SST];

// ================= low-level helpers (sm_80-baseline PTX only) =================
__device__ __forceinline__ uint32_t smem_u32(const void* p) {
    uint32_t a;
    asm("{ .reg .u64 t; cvta.to.shared.u64 t, %1; cvt.u32.u64 %0, t; }" : "=r"(a) : "l"(p));
    return a;
}
__device__ __forceinline__ void cp16(uint32_t dst, const void* src) {
    asm volatile("cp.async.cg.shared.global [%0], [%1], 16;" :: "r"(dst), "l"(src));
}
#define CP_COMMIT()  asm volatile("cp.async.commit_group;" ::: "memory")
#define CP_WAIT1()   asm volatile("cp.async.wait_group 1;" ::: "memory")

__device__ __forceinline__ void ldsm4(uint32_t* r, uint32_t addr) {
    asm volatile("ldmatrix.sync.aligned.m8n8.x4.shared.b16 {%0,%1,%2,%3}, [%4];"
                 : "=r"(r[0]), "=r"(r[1]), "=r"(r[2]), "=r"(r[3]) : "r"(addr));
}
__device__ __forceinline__ void mma16816(float* c, const uint32_t* a, uint32_t b0, uint32_t b1) {
    asm volatile(
        "mma.sync.aligned.m16n8k16.row.col.f32.f16.f16.f32 "
        "{%0,%1,%2,%3}, {%4,%5,%6,%7}, {%8,%9}, {%0,%1,%2,%3};"
        : "+f"(c[0]), "+f"(c[1]), "+f"(c[2]), "+f"(c[3])
        : "r"(a[0]), "r"(a[1]), "r"(a[2]), "r"(a[3]), "r"(b0), "r"(b1));
}

// ================= GEMM parameter block (per grid.z) =================
struct GArg {
    const __half *A0;                  // A source 0 (cols [0, K0))
    const __half *A1;                  // A source 1 (cols [K0, K)) or null
    int lda0, lda1, K0, K;
    const __half *Wh, *Wl;             // W [N, K] row-major, fp16 hi/lo
    int ldw;
    const float* bias;
    float* C;                          // fp32 out (if !HOUT)
    __half* Ch;                        // fp16 out (if HOUT)
    int N;
};

// ================= warp-MMA split-fp16 GEMM =================
// C[2048, N] = act( [A0|A1] @ (Wh+Wl)^T + bias ), 2-term: A*Wh + A*Wl, fp32 acc.
// CTA tile 128x64, 8 warps in 4M x 2N grid of 32x32 warp tiles, BK=32.
// R17: 3-stage pipeline, 3 CTAs/SM (launch_bounds(256,3), reg cap ~85), and a
// running-pointer loader (4 persistent gmem ptrs, +32 halfs/chunk, one-shot
// reset at the A0->A1 seam) to cut addressing ALU + live registers.
#define LDSW    40                       // smem row stride in fp16 (32 + 8 pad)
#define TSA     (128 * LDSW * 2)         // A tile bytes (10240)
#define TSW     (64 * LDSW * 2)          // W tile bytes (5120)
#define STAGE_B (TSA + 2u * TSW)         // A, Wh, Wl (20480 B)
#define NSTAGE  3
#define SMEM_SZ (NSTAGE * STAGE_B)       // 61440 B -> 3 CTAs/SM

template <bool RELU, bool HOUT>
__global__ __launch_bounds__(256, 3)
void mma_gemm2(GArg ga, GArg gb)
{
    const GArg g = (blockIdx.z == 0) ? ga : gb;

    extern __shared__ char smem_raw[];
    const uint32_t sb0 = smem_u32(smem_raw);

    const int tid = threadIdx.x;
    const int lane = tid & 31, wid = tid >> 5;
    const int wm = wid & 3, wn = wid >> 2;          // 4M x 2N warp grid, 32x32 tiles
    const int row0 = blockIdx.y * 128, col0 = blockIdx.x * 64;

    // ---- loader persistent state (running pointers) ----
    const int lr = tid >> 2, lc4 = tid & 3;          // lr: 0..63, lc4: 0..3
    const uint32_t sA0 = (uint32_t)(lr * (LDSW * 2) + lc4 * 16);           // A rows 0..63
    const uint32_t sA1 = sA0 + (uint32_t)(64 * LDSW * 2);                  // A rows 64..127
    const uint32_t sW  = sA0;                                              // W rows 0..63
    const __half* aptr  = g.A0 + (size_t)(row0 + lr) * g.lda0 + lc4 * 8;       // A row lr
    const __half* aptr2 = g.A0 + (size_t)(row0 + 64 + lr) * g.lda0 + lc4 * 8;  // A row 64+lr
    const __half* whp   = g.Wh + (size_t)(col0 + lr) * g.ldw + lc4 * 8;
    const __half* wlp   = g.Wl + (size_t)(col0 + lr) * g.ldw + lc4 * 8;
    const int cs = g.K0 >> 5;                        // chunk index where A1 begins
    const int NC = g.K >> 5;                         // min K = 288 -> NC = 9

    auto issue_chunk = [&](int c, uint32_t sbase) {
        if (c == cs) {                               // A0 -> A1 seam (never taken if K0==K)
            aptr  = g.A1 + (size_t)(row0 + lr) * g.lda1 + lc4 * 8;
            aptr2 = g.A1 + (size_t)(row0 + 64 + lr) * g.lda1 + lc4 * 8;
        }
        cp16(sbase + sA0,             aptr);
        cp16(sbase + sA1,             aptr2);
        cp16(sbase + TSA + sW,        whp);
        cp16(sbase + TSA + TSW + sW,  wlp);
        aptr += 32; aptr2 += 32; whp += 32; wlp += 32;
    };

    float acc[2][4][4];
#pragma unroll
    for (int a = 0; a < 2; a++)
#pragma unroll
        for (int b = 0; b < 4; b++)
#pragma unroll
            for (int c = 0; c < 4; c++) acc[a][b][c] = 0.0f;

    // prefetch chunks 0, 1
    issue_chunk(0, sb0);           CP_COMMIT();
    issue_chunk(1, sb0 + STAGE_B); CP_COMMIT();

    const int lrow = lane & 15;
    const int lcol = (lane >> 4) << 3;

    uint32_t stage = 0;            // byte offset of current stage, cycles 0, S, 2S
    for (int c = 0; c < NC; c++) {
        CP_WAIT1();                // chunk c complete (c+1 may be in flight)
        __syncthreads();           // visible to all; iter c-1 compute done

        // prefetch chunk c+2 into buffer (c+2)%3 (= buffer of c-1; safe after sync)
        const int pf = c + 2;
        if (pf < NC) {
            uint32_t pfs = stage + 2 * STAGE_B;
            if (pfs >= (uint32_t)SMEM_SZ) pfs -= (uint32_t)SMEM_SZ;
            issue_chunk(pf, sb0 + pfs);
        }
        CP_COMMIT();

        const uint32_t st = sb0 + stage;
        stage += STAGE_B; if (stage >= (uint32_t)SMEM_SZ) stage = 0;

#pragma unroll
        for (int k16 = 0; k16 < 32; k16 += 16) {
            uint32_t av[2][4], wh[2][4], wl[2][4];
#pragma unroll
            for (int mt = 0; mt < 2; mt++) {
                uint32_t ra = (uint32_t)((wm * 32 + mt * 16 + lrow) * LDSW + k16 + lcol) * 2;
                ldsm4(av[mt], st + ra);
            }
#pragma unroll
            for (int gg = 0; gg < 2; gg++) {
                uint32_t rb = (uint32_t)((wn * 32 + gg * 16 + lrow) * LDSW + k16 + lcol) * 2;
                ldsm4(wh[gg], st + TSA + rb);
                ldsm4(wl[gg], st + TSA + TSW + rb);
            }
#pragma unroll
            for (int mt = 0; mt < 2; mt++)
#pragma unroll
                for (int gg = 0; gg < 2; gg++)
#pragma unroll
                    for (int h = 0; h < 2; h++)
                        mma16816(acc[mt][gg * 2 + h], av[mt], wh[gg][h], wh[gg][h + 2]);
#pragma unroll
            for (int mt = 0; mt < 2; mt++)
#pragma unroll
                for (int gg = 0; gg < 2; gg++)
#pragma unroll
                    for (int h = 0; h < 2; h++)
                        mma16816(acc[mt][gg * 2 + h], av[mt], wl[gg][h], wl[gg][h + 2]);
        }
        // no end-of-loop sync: next iteration's top sync provides the WAR barrier
    }

    // ---- epilogue (vectorized stores) ----
    const int gid = lane >> 2, tig = lane & 3;
#pragma unroll
    for (int mt = 0; mt < 2; mt++) {
        const int ra = row0 + wm * 32 + mt * 16 + gid;
#pragma unroll
        for (int nt = 0; nt < 4; nt++) {
            const int col = col0 + wn * 32 + nt * 8 + tig * 2;
            const float b0 = g.bias[col], b1 = g.bias[col + 1];
            const float* cc = acc[mt][nt];
#pragma unroll
            for (int half = 0; half < 2; half++) {
                const int r = ra + half * 8;
                float v0 = cc[half * 2 + 0] + b0;
                float v1 = cc[half * 2 + 1] + b1;
                if (RELU) { v0 = fmaxf(v0, 0.0f); v1 = fmaxf(v1, 0.0f); }
                const size_t o = (size_t)r * g.N + col;
                if (HOUT) {
                    *reinterpret_cast<__half2*>(g.Ch + o) = __floats2half2_rn(v0, v1);
                } else {
                    *reinterpret_cast<float2*>(g.C + o) = make_float2(v0, v1);
                }
            }
        }
    }
}

// ================= merged conversion kernels =================
struct WSeg { const float* src[7]; __half* hi[7]; __half* lo[7]; int blk0[8]; int size[7]; };
__global__ void conv_wsplit_all(WSeg a)
{
    int blk = blockIdx.x, s = 0;
#pragma unroll
    for (int i = 1; i < 7; i++) if (blk >= a.blk0[i]) s = i;
    int i = (blk - a.blk0[s]) * 256 + threadIdx.x;
    if (i < a.size[s]) {
        float x = a.src[s][i];
        __half h = __float2half_rn(x);
        a.hi[s][i] = h;
        a.lo[s][i] = __float2half_rn(x - __half2float(h));
    }
}

struct HSeg { const float* src[4]; __half* dst[4]; int blk0[5]; int size[4]; };
__global__ void conv_h_all(HSeg a)
{
    int blk = blockIdx.x, s = 0;
#pragma unroll
    for (int i = 1; i < 4; i++) if (blk >= a.blk0[i]) s = i;
    int i = (blk - a.blk0[s]) * 256 + threadIdx.x;
    if (i < a.size[s]) a.dst[s][i] = __float2half_rn(a.src[s][i]);
}

// ================= elementwise step kernels =================
__global__ void gru_combine(const float* __restrict__ gi, const float* __restrict__ gh,
                            const float* __restrict__ hprev, float* __restrict__ hout,
                            __half* __restrict__ bel_half)
{
    int i = blockIdx.x * blockDim.x + threadIdx.x;
    if (i >= BB * BEL) return;
    int b = i >> 10, c = i & 1023;
    const float* gib = gi + (size_t)b * 3 * BEL;
    const float* ghb = gh + (size_t)b * 3 * BEL;
    float ir = gib[c],           hr = ghb[c];
    float iz = gib[BEL + c],     hz = ghb[BEL + c];
    float in = gib[2 * BEL + c], hn = ghb[2 * BEL + c];
    float r = 1.0f / (1.0f + expf(-(ir + hr)));
    float z = 1.0f / (1.0f + expf(-(iz + hz)));
    float n = tanhf(in + r * hn);
    float h = (1.0f - z) * n + z * hprev[i];
    hout[i] = h;
    bel_half[i] = __float2half_rn(h);
}

__global__ void head_epi2(const float* __restrict__ pout, const float* __restrict__ qout,
                          const float* __restrict__ pn, const float* __restrict__ qn,
                          float* __restrict__ o_ps, float* __restrict__ o_pm, float* __restrict__ o_pstd,
                          float* __restrict__ o_qs, float* __restrict__ o_qm, float* __restrict__ o_qstd,
                          __half* __restrict__ st_half)
{
    int i = blockIdx.x * blockDim.x + threadIdx.x;
    if (i >= 2 * BB * SST) return;
    const bool isq = i >= BB * SST;
    const int j = isq ? i - BB * SST : i;
    const int b = j >> 8, c = j & 255;
    const float* src = isq ? qout : pout;
    float m  = src[(size_t)b * 2 * SST + c];
    float lg = src[(size_t)b * 2 * SST + SST + c];
    float y  = expf(lg);
    float sp = (y > 20.0f) ? y : log1pf(expf(y));
    float sd = sp + 0.1f;
    float ns = isq ? qn[j] : pn[j];
    float stv = m + sd * ns;
    if (isq) {
        o_qm[j] = m; o_qstd[j] = sd; o_qs[j] = stv;
        st_half[j] = __float2half_rn(stv);
    } else {
        o_pm[j] = m; o_pstd[j] = sd; o_ps[j] = stv;
    }
}

// ================= host dispatch =================
static inline GArg mk(const __half* A0, int lda0, int K0,
                      const __half* A1, int lda1, int K,
                      const __half* Wh, const __half* Wl, int ldw,
                      const float* bias, int N,
                      float* C, __half* Ch)
{
    GArg g;
    g.A0 = A0; g.A1 = A1;
    g.lda0 = lda0; g.lda1 = lda1; g.K0 = K0; g.K = K;
    g.Wh = Wh; g.Wl = Wl; g.ldw = ldw; g.bias = bias;
    g.C = C; g.Ch = Ch; g.N = N;
    return g;
}

extern "C" void kernel_launch(void* const* d_in, const int* in_sizes, int n_in,
                              void* d_out, int out_size)
{
    const float* prev_state   = (const float*)d_in[0];
    const float* actions      = (const float*)d_in[1];
    const float* prev_belief  = (const float*)d_in[2];
    const float* observations = (const float*)d_in[3];
    const float* prior_noise  = (const float*)d_in[4];
    const float* post_noise   = (const float*)d_in[5];
    const float* W_sa = (const float*)d_in[6];
    const float* b_sa = (const float*)d_in[7];
    const float* W_ih = (const float*)d_in[8];
    const float* W_hh = (const float*)d_in[9];
    const float* b_ih = (const float*)d_in[10];
    const float* b_hh = (const float*)d_in[11];
    const float* W_pb = (const float*)d_in[12];
    const float* b_pb = (const float*)d_in[13];
    const float* W_ps = (const float*)d_in[14];
    const float* b_ps = (const float*)d_in[15];
    const float* W_qb = (const float*)d_in[16];
    const float* b_qb = (const float*)d_in[17];
    const float* W_qs = (const float*)d_in[18];
    const float* b_qs = (const float*)d_in[19];

    float* out = (float*)d_out;
    float* out_bel  = out;
    float* out_ps   = out_bel  + (size_t)TT * BB * BEL;
    float* out_pm   = out_ps   + (size_t)TT * BB * SST;
    float* out_pstd = out_pm   + (size_t)TT * BB * SST;
    float* out_qs   = out_pstd + (size_t)TT * BB * SST;
    float* out_qm   = out_qs   + (size_t)TT * BB * SST;
    float* out_qstd = out_qm   + (size_t)TT * BB * SST;

    cudaFuncSetAttribute(mma_gemm2<true, true>,   cudaFuncAttributeMaxDynamicSharedMemorySize, SMEM_SZ);
    cudaFuncSetAttribute(mma_gemm2<false, false>, cudaFuncAttributeMaxDynamicSharedMemorySize, SMEM_SZ);

    __half *Wsa_h, *Wsa_l, *Wih_h, *Wih_l, *Whh_h, *Whh_l, *Wpb_h, *Wpb_l,
           *Wps_h, *Wps_l, *Wqb_h, *Wqb_l, *Wqs_h, *Wqs_l,
           *act, *obs, *st, *rnn, *bel, *ph, *qh;
    float *gi, *gh, *pout, *qout;
    cudaGetSymbolAddress((void**)&Wsa_h, g_Wsa_h); cudaGetSymbolAddress((void**)&Wsa_l, g_Wsa_l);
    cudaGetSymbolAddress((void**)&Wih_h, g_Wih_h); cudaGetSymbolAddress((void**)&Wih_l, g_Wih_l);
    cudaGetSymbolAddress((void**)&Whh_h, g_Whh_h); cudaGetSymbolAddress((void**)&Whh_l, g_Whh_l);
    cudaGetSymbolAddress((void**)&Wpb_h, g_Wpb_h); cudaGetSymbolAddress((void**)&Wpb_l, g_Wpb_l);
    cudaGetSymbolAddress((void**)&Wps_h, g_Wps_h); cudaGetSymbolAddress((void**)&Wps_l, g_Wps_l);
    cudaGetSymbolAddress((void**)&Wqb_h, g_Wqb_h); cudaGetSymbolAddress((void**)&Wqb_l, g_Wqb_l);
    cudaGetSymbolAddress((void**)&Wqs_h, g_Wqs_h); cudaGetSymbolAddress((void**)&Wqs_l, g_Wqs_l);
    cudaGetSymbolAddress((void**)&act, g_act); cudaGetSymbolAddress((void**)&obs, g_obs);
    cudaGetSymbolAddress((void**)&st,  g_st);  cudaGetSymbolAddress((void**)&rnn, g_rnn);
    cudaGetSymbolAddress((void**)&bel, g_bel); cudaGetSymbolAddress((void**)&ph,  g_ph);
    cudaGetSymbolAddress((void**)&qh,  g_qh);
    cudaGetSymbolAddress((void**)&gi,   g_gi);   cudaGetSymbolAddress((void**)&gh,   g_gh);
    cudaGetSymbolAddress((void**)&pout, g_pout); cudaGetSymbolAddress((void**)&qout, g_qout);

    // ---- merged one-time conversions (2 launches) ----
    {
        WSeg w;
        const float* srcs[7] = {W_sa, W_ih, W_hh, W_pb, W_ps, W_qb, W_qs};
        __half* his[7] = {Wsa_h, Wih_h, Whh_h, Wpb_h, Wps_h, Wqb_h, Wqs_h};
        __half* los[7] = {Wsa_l, Wih_l, Whh_l, Wpb_l, Wps_l, Wqb_l, Wqs_l};
        int sizes[7] = {1024 * KSA2, 3072 * 1024, 3072 * 1024, 1024 * 1024,
                        512 * 1024, 1024 * 2048, 512 * 1024};
        int cum = 0;
        for (int i = 0; i < 7; i++) {
            w.src[i] = srcs[i]; w.hi[i] = his[i]; w.lo[i] = los[i]; w.size[i] = sizes[i];
            w.blk0[i] = cum; cum += (sizes[i] + 255) / 256;
        }
        w.blk0[7] = cum;
        conv_wsplit_all<<<cum, 256>>>(w);
    }
    {
        HSeg h;
        const float* srcs[4] = {actions, observations, prev_state, prev_belief};
        __half* dsts[4] = {act, obs, st, bel};
        int sizes[4] = {TT * BB * AAC, TT * BB * EMB, BB * SST, BB * BEL};
        int cum = 0;
        for (int i = 0; i < 4; i++) {
            h.src[i] = srcs[i]; h.dst[i] = dsts[i]; h.size[i] = sizes[i];
            h.blk0[i] = cum; cum += (sizes[i] + 255) / 256;
        }
        h.blk0[4] = cum;
        conv_h_all<<<cum, 256>>>(h);
    }

    // grids: x = N/64, y = M/128, z = batched pair
    const dim3 g_sa(16, 16, 1), g_gate(48, 16, 2), g_pq(16, 16, 2), g_ss(8, 16, 2);
    const int nb_bel = (BB * BEL) / 256, nb_head2 = (2 * BB * SST) / 256;

    for (int t = 0; t < TT; t++) {
        const __half* a_t = act + (size_t)t * BB * AAC;
        const __half* o_t = obs + (size_t)t * BB * EMB;
        const float* pn_t = prior_noise + (size_t)t * BB * SST;
        const float* qn_t = post_noise  + (size_t)t * BB * SST;
        const float* bel_prev_f32 = (t == 0) ? prev_belief
                                             : out_bel + (size_t)(t - 1) * BB * BEL;
        float* bel_t = out_bel + (size_t)t * BB * BEL;

        // 1. rnn_in = relu([state | action] @ W_sa^T + b_sa) -> fp16
        {
            GArg a = mk(st, SST, SST, a_t, AAC, KSA2,
                        Wsa_h, Wsa_l, KSA2, b_sa, BEL, nullptr, rnn);
            mma_gemm2<true, true><<<g_sa, 256, SMEM_SZ>>>(a, a);
        }
        // 2. GRU gates, batched: z0 gi = rnn@W_ih^T, z1 gh = bel@W_hh^T
        {
            GArg a = mk(rnn, BEL, BEL, nullptr, 0, BEL,
                        Wih_h, Wih_l, BEL, b_ih, 3 * BEL, gi, nullptr);
            GArg b = mk(bel, BEL, BEL, nullptr, 0, BEL,
                        Whh_h, Whh_l, BEL, b_hh, 3 * BEL, gh, nullptr);
            mma_gemm2<false, false><<<g_gate, 256, SMEM_SZ>>>(a, b);
        }
        gru_combine<<<nb_bel, 256>>>(gi, gh, bel_prev_f32, bel_t, bel);

        // 3. hidden heads, batched: z0 ph = relu(bel@W_pb^T), z1 qh = relu([bel|obs]@W_qb^T)
        {
            GArg a = mk(bel, BEL, BEL, nullptr, 0, BEL,
                        Wpb_h, Wpb_l, BEL, b_pb, HID, nullptr, ph);
            GArg b = mk(bel, BEL, BEL, o_t, EMB, BEL + EMB,
                        Wqb_h, Wqb_l, BEL + EMB, b_qb, HID, nullptr, qh);
            mma_gemm2<true, true><<<g_pq, 256, SMEM_SZ>>>(a, b);
        }
        // 4. stat heads, batched: z0 pout = ph@W_ps^T, z1 qout = qh@W_qs^T
        {
            GArg a = mk(ph, HID, HID, nullptr, 0, HID,
                        Wps_h, Wps_l, HID, b_ps, 2 * SST, pout, nullptr);
            GArg b = mk(qh, HID, HID, nullptr, 0, HID,
                        Wqs_h, Wqs_l, HID, b_qs, 2 * SST, qout, nullptr);
            mma_gemm2<false, false><<<g_ss, 256, SMEM_SZ>>>(a, b);
        }
        // 5. both head epilogues + next-step state
        head_epi2<<<nb_head2, 256>>>(pout, qout, pn_t, qn_t,
                                     out_ps   + (size_t)t * BB * SST,
                                     out_pm   + (size_t)t * BB * SST,
                                     out_pstd + (size_t)t * BB * SST,
                                     out_qs   + (size_t)t * BB * SST,
                                     out_qm   + (size_t)t * BB * SST,
                                     out_qstd + (size_t)t * BB * SST,
                                     st);
    }
}